// round 1
// baseline (speedup 1.0000x reference)
#include <cuda_runtime.h>
#include <cstdint>

#define HW 2
#define H 512
#define W 512
#define BX 32
#define BY 8
#define TILE_W (BX + 2*HW)   // 36
#define TILE_H (BY + 2*HW)   // 12

// scratch for the intermediate passes (allocation-free rule -> device globals)
__device__ float g_buf0[32 * H * W];
__device__ float g_buf1[32 * H * W];

__device__ __forceinline__ float ex2_approx(float x) {
    float y;
    asm("ex2.approx.ftz.f32 %0, %1;" : "=f"(y) : "f"(x));
    return y;
}

__global__ __launch_bounds__(BX * BY) void bilateral_pass(
    const float* __restrict__ in, float* __restrict__ out,
    const float* __restrict__ sigma_xyz, const float* __restrict__ sigma_r,
    int pass)
{
    __shared__ float tile[TILE_H][TILE_W];

    const int bx = blockIdx.x * BX;
    const int by = blockIdx.y * BY;
    const int b  = blockIdx.z;
    const float* img = in + (size_t)b * (H * W);

    // cooperative tile load with replicate (clamp) padding
    const int t = threadIdx.y * BX + threadIdx.x;
    #pragma unroll
    for (int idx = t; idx < TILE_W * TILE_H; idx += BX * BY) {
        int ly = idx / TILE_W;
        int lx = idx - ly * TILE_W;
        int gx = bx + lx - HW;
        int gy = by + ly - HW;
        gx = min(max(gx, 0), W - 1);
        gy = min(max(gy, 0), H - 1);
        tile[ly][lx] = img[gy * W + gx];
    }

    // per-pass constants (broadcast loads, cheap)
    const float LOG2E = 1.4426950408889634f;
    const float sx = sigma_xyz[2 * pass + 0];
    const float sy = sigma_xyz[2 * pass + 1];
    const float sr = sigma_r[pass];
    const float ax = 0.5f / (sx * sx) * LOG2E;   // spatial x coeff (log2 domain)
    const float ay = 0.5f / (sy * sy) * LOG2E;   // spatial y coeff
    const float ar = 0.5f / (sr * sr) * LOG2E;   // range coeff

    // log2-domain spatial weights for offsets -2..2
    const float wxs[5] = { -4.0f * ax, -ax, 0.0f, -ax, -4.0f * ax };
    const float wys[5] = { -4.0f * ay, -ay, 0.0f, -ay, -4.0f * ay };

    __syncthreads();

    const int tx = threadIdx.x;
    const int ty = threadIdx.y;
    const float c = tile[ty + HW][tx + HW];

    float num = 0.0f;
    float den = 0.0f;

    #pragma unroll
    for (int dy = 0; dy < 5; dy++) {
        const float sy_log2 = wys[dy];
        #pragma unroll
        for (int dx = 0; dx < 5; dx++) {
            const float s = sy_log2 + wxs[dx];     // hoisted/CSE'd: 9 distinct values
            const float nb = tile[ty + dy][tx + dx];
            const float d  = nb - c;
            const float arg = fmaf(d * d, -ar, s); // log2-domain combined weight
            const float w = ex2_approx(arg);       // single MUFU.EX2 per neighbor
            num = fmaf(w, nb, num);
            den += w;
        }
    }

    out[(size_t)b * (H * W) + (by + ty) * W + (bx + tx)] = __fdividef(num, den);
}

extern "C" void kernel_launch(void* const* d_in, const int* in_sizes, int n_in,
                              void* d_out, int out_size)
{
    const float* x         = (const float*)d_in[0];
    const float* sigma_xyz = (const float*)d_in[1];
    const float* sigma_r   = (const float*)d_in[2];
    float* out = (float*)d_out;

    const int B = in_sizes[0] / (H * W);

    float* buf0;
    float* buf1;
    cudaGetSymbolAddress((void**)&buf0, g_buf0);
    cudaGetSymbolAddress((void**)&buf1, g_buf1);

    dim3 block(BX, BY, 1);
    dim3 grid(W / BX, H / BY, B);

    // pass 0: x -> buf0, pass 1: buf0 -> buf1, pass 2: buf1 -> out
    bilateral_pass<<<grid, block>>>(x,    buf0, sigma_xyz, sigma_r, 0);
    bilateral_pass<<<grid, block>>>(buf0, buf1, sigma_xyz, sigma_r, 1);
    bilateral_pass<<<grid, block>>>(buf1, out,  sigma_xyz, sigma_r, 2);
}

// round 2
// speedup vs baseline: 1.4250x; 1.4250x over previous
#include <cuda_runtime.h>
#include <cstdint>

#define HW 2
#define H 512
#define W 512
#define BX 32
#define BY 8
#define TILE_W (BX + 2*HW)   // 36
#define TILE_H (BY + 2*HW)   // 12

// scratch for the intermediate passes (allocation-free rule -> device globals)
__device__ float g_buf0[32 * H * W];
__device__ float g_buf1[32 * H * W];

__device__ __forceinline__ float ex2_approx(float x) {
    float y;
    asm("ex2.approx.ftz.f32 %0, %1;" : "=f"(y) : "f"(x));
    return y;
}

__global__ __launch_bounds__(BX * BY) void bilateral_pass(
    const float* __restrict__ in, float* __restrict__ out,
    const float* __restrict__ sigma_xyz, const float* __restrict__ sigma_r,
    int pass)
{
    __shared__ float tile[TILE_H][TILE_W];

    const int bx = blockIdx.x * BX;
    const int by = blockIdx.y * BY;
    const int b  = blockIdx.z;
    const float* img = in + (size_t)b * (H * W);

    // cooperative tile load with replicate (clamp) padding
    const int t = threadIdx.y * BX + threadIdx.x;
    #pragma unroll
    for (int k = 0; k < 2; k++) {
        int idx = t + k * (BX * BY);
        if (idx < TILE_W * TILE_H) {
            int ly = idx / TILE_W;
            int lx = idx - ly * TILE_W;
            int gx = min(max(bx + lx - HW, 0), W - 1);
            int gy = min(max(by + ly - HW, 0), H - 1);
            tile[ly][lx] = img[gy * W + gx];
        }
    }

    // per-pass constants (broadcast loads)
    const float LOG2E = 1.4426950408889634f;
    const float sx = sigma_xyz[2 * pass + 0];
    const float sy = sigma_xyz[2 * pass + 1];
    const float sr = sigma_r[pass];
    const float axn = 0.5f / (sx * sx);          // natural-log spatial coeffs
    const float ayn = 0.5f / (sy * sy);
    const float axl = axn * LOG2E;               // log2 domain
    const float ayl = ayn * LOG2E;
    const float ar  = (0.5f / (sr * sr)) * LOG2E;
    const float nar = -ar;

    // adaptive outer-ring truncation: bound the normalized error from dropping
    // the 16 |dx|=2 or |dy|=2 taps. Per dropped tap the contribution error is
    // <= ws * max_d(d * exp(-d^2/(2 sr^2))) = ws * sr * e^{-1/2}; den >= 1.
    const float w1x = __expf(-axn), w4x = __expf(-4.f * axn);
    const float w1y = __expf(-ayn), w4y = __expf(-4.f * ayn);
    const float ring = 2.f * w4x * (1.f + 2.f * w1y + 2.f * w4y)
                     + 2.f * w4y * (1.f + 2.f * w1x);
    const bool need_outer = !(ring * 0.6065307f * sr < 1e-4f);

    __syncthreads();

    const int tx = threadIdx.x;
    const int ty = threadIdx.y;
    const float c = tile[ty + HW][tx + HW];

    // expanded quadratic: arg = -ar*nb^2 + 2*ar*c*nb + (s - ar*c^2)
    const float t1 = 2.0f * ar * c;
    const float t0 = nar * c * c;
    // per-class constants (log2-domain spatial weight + t0)
    const float t10 = t0 - axl;                // (|dx|=1, dy=0)
    const float t01 = t0 - ayl;                // (dx=0, |dy|=1)
    const float t11 = t0 - (axl + ayl);        // (|dx|=1, |dy|=1)
    const float t20 = t0 - 4.f * axl;
    const float t02 = t0 - 4.f * ayl;
    const float t21 = t0 - (4.f * axl + ayl);
    const float t12 = t0 - (axl + 4.f * ayl);
    const float t22 = t0 - 4.f * (axl + ayl);

    // center tap: arg == 0 -> w == 1 exactly
    float num = c;
    float den = 1.0f;

    #define DO_NB(DY, DX, T0C) {                                   \
        const float nb = tile[ty + HW + (DY)][tx + HW + (DX)];      \
        const float u  = fmaf(nb, nar, t1);                         \
        const float w  = ex2_approx(fmaf(nb, u, (T0C)));            \
        num = fmaf(w, nb, num);                                     \
        den += w;                                                   \
    }

    // inner 3x3 ring (8 taps)
    DO_NB(-1, -1, t11)  DO_NB(-1, 0, t01)  DO_NB(-1, 1, t11)
    DO_NB( 0, -1, t10)                     DO_NB( 0, 1, t10)
    DO_NB( 1, -1, t11)  DO_NB( 1, 0, t01)  DO_NB( 1, 1, t11)

    if (need_outer) {
        // outer ring (16 taps)
        DO_NB(-2, -2, t22) DO_NB(-2, -1, t12) DO_NB(-2, 0, t02) DO_NB(-2, 1, t12) DO_NB(-2, 2, t22)
        DO_NB(-1, -2, t21)                                                        DO_NB(-1, 2, t21)
        DO_NB( 0, -2, t20)                                                        DO_NB( 0, 2, t20)
        DO_NB( 1, -2, t21)                                                        DO_NB( 1, 2, t21)
        DO_NB( 2, -2, t22) DO_NB( 2, -1, t12) DO_NB( 2, 0, t02) DO_NB( 2, 1, t12) DO_NB( 2, 2, t22)
    }
    #undef DO_NB

    out[(size_t)b * (H * W) + (by + ty) * W + (bx + tx)] = __fdividef(num, den);
}

extern "C" void kernel_launch(void* const* d_in, const int* in_sizes, int n_in,
                              void* d_out, int out_size)
{
    const float* x         = (const float*)d_in[0];
    const float* sigma_xyz = (const float*)d_in[1];
    const float* sigma_r   = (const float*)d_in[2];
    float* out = (float*)d_out;

    const int B = in_sizes[0] / (H * W);

    float* buf0;
    float* buf1;
    cudaGetSymbolAddress((void**)&buf0, g_buf0);
    cudaGetSymbolAddress((void**)&buf1, g_buf1);

    dim3 block(BX, BY, 1);
    dim3 grid(W / BX, H / BY, B);

    bilateral_pass<<<grid, block>>>(x,    buf0, sigma_xyz, sigma_r, 0);
    bilateral_pass<<<grid, block>>>(buf0, buf1, sigma_xyz, sigma_r, 1);
    bilateral_pass<<<grid, block>>>(buf1, out,  sigma_xyz, sigma_r, 2);
}

// round 3
// speedup vs baseline: 2.3954x; 1.6810x over previous
#include <cuda_runtime.h>
#include <cstdint>

#define HW 2
#define H 512
#define W 512
#define BX 32
#define BY 4
#define PPT 8                       // pixels per thread (vertical strip)
#define BLKY (BY * PPT)             // 32 rows covered per block
#define TILE_W (BX + 2*HW)          // 36
#define TILE_H (BLKY + 2*HW)        // 36

// scratch for the intermediate passes (allocation-free rule -> device globals)
__device__ float g_buf0[32 * H * W];
__device__ float g_buf1[32 * H * W];

__device__ __forceinline__ float ex2_approx(float x) {
    float y;
    asm("ex2.approx.ftz.f32 %0, %1;" : "=f"(y) : "f"(x));
    return y;
}

__global__ __launch_bounds__(BX * BY) void bilateral_pass(
    const float* __restrict__ in, float* __restrict__ out,
    const float* __restrict__ sigma_xyz, const float* __restrict__ sigma_r,
    int pass)
{
    __shared__ float tile[TILE_H][TILE_W];

    const int bx = blockIdx.x * BX;
    const int by = blockIdx.y * BLKY;
    const int b  = blockIdx.z;
    const float* img = in + (size_t)b * (H * W);

    // cooperative tile load with replicate (clamp) padding
    const int t = threadIdx.y * BX + threadIdx.x;
    #pragma unroll
    for (int k = 0; k < (TILE_W * TILE_H + BX*BY - 1) / (BX*BY); k++) {
        int idx = t + k * (BX * BY);
        if (idx < TILE_W * TILE_H) {
            int ly = idx / TILE_W;
            int lx = idx - ly * TILE_W;
            int gx = min(max(bx + lx - HW, 0), W - 1);
            int gy = min(max(by + ly - HW, 0), H - 1);
            tile[ly][lx] = img[gy * W + gx];
        }
    }

    // per-pass constants (broadcast loads)
    const float LOG2E = 1.4426950408889634f;
    const float sx = sigma_xyz[2 * pass + 0];
    const float sy = sigma_xyz[2 * pass + 1];
    const float sr = sigma_r[pass];
    const float axn = 0.5f / (sx * sx);          // natural-log spatial coeffs
    const float ayn = 0.5f / (sy * sy);
    const float axl = axn * LOG2E;               // log2 domain
    const float ayl = ayn * LOG2E;
    const float ar  = (0.5f / (sr * sr)) * LOG2E;
    const float nar = -ar;
    const float twoar = 2.0f * ar;
    const float axyl = axl + ayl;
    const float a4x = 4.f * axl, a4y = 4.f * ayl;

    // adaptive outer-ring truncation: bound the normalized error from dropping
    // the 16 |dx|=2 or |dy|=2 taps. Per dropped tap the contribution error is
    // <= ws * max_d(d * exp(-d^2/(2 sr^2))) = ws * sr * e^{-1/2}; den >= 1.
    const float w1x = __expf(-axn), w4x = __expf(-4.f * axn);
    const float w1y = __expf(-ayn), w4y = __expf(-4.f * ayn);
    const float ring = 2.f * w4x * (1.f + 2.f * w1y + 2.f * w4y)
                     + 2.f * w4y * (1.f + 2.f * w1x);
    const bool need_outer = !(ring * 0.6065307f * sr < 1e-4f);

    __syncthreads();

    const int tx = threadIdx.x;
    const int y0 = threadIdx.y * PPT;            // first local pixel row
    const int cx = tx + HW;                      // center column in tile

    // rolling 3-row register window over columns cx-1..cx+1
    float ra[3], rb[3], rc[3];
    #pragma unroll
    for (int j = 0; j < 3; j++) {
        ra[j] = tile[y0 + HW - 1][cx - 1 + j];
        rb[j] = tile[y0 + HW    ][cx - 1 + j];
    }

    float* orow = out + (size_t)b * (H * W) + (by + y0) * W + (bx + tx);

    #pragma unroll
    for (int r = 0; r < PPT; r++) {
        const int py = y0 + HW + r;              // tile row of this pixel
        #pragma unroll
        for (int j = 0; j < 3; j++)
            rc[j] = tile[py + 1][cx - 1 + j];

        const float c  = rb[1];
        const float t1 = twoar * c;
        const float t0 = nar * c * c;
        const float t10 = t0 - axl;
        const float t01 = t0 - ayl;
        const float t11 = t0 - axyl;

        // center tap: arg == 0 -> w == 1 exactly
        float num = c;
        float den = 1.0f;

        #define DO_R(NB, T0C) {                          \
            const float nb = (NB);                       \
            const float u  = fmaf(nb, nar, t1);          \
            const float w  = ex2_approx(fmaf(nb, u, (T0C))); \
            num = fmaf(w, nb, num);                      \
            den += w;                                    \
        }
        DO_R(ra[0], t11) DO_R(ra[1], t01) DO_R(ra[2], t11)
        DO_R(rb[0], t10)                  DO_R(rb[2], t10)
        DO_R(rc[0], t11) DO_R(rc[1], t01) DO_R(rc[2], t11)

        if (need_outer) {
            // full 5x5 fallback: outer ring (16 taps) straight from smem
            const float t20 = t0 - a4x;
            const float t02 = t0 - a4y;
            const float t21 = t0 - (a4x + ayl);
            const float t12 = t0 - (axl + a4y);
            const float t22 = t0 - (a4x + a4y);
            #define DO_S(DY, DX, T0C) DO_R(tile[py + (DY)][cx + (DX)], T0C)
            DO_S(-2, -2, t22) DO_S(-2, -1, t12) DO_S(-2, 0, t02) DO_S(-2, 1, t12) DO_S(-2, 2, t22)
            DO_S(-1, -2, t21)                                                     DO_S(-1, 2, t21)
            DO_S( 0, -2, t20)                                                     DO_S( 0, 2, t20)
            DO_S( 1, -2, t21)                                                     DO_S( 1, 2, t21)
            DO_S( 2, -2, t22) DO_S( 2, -1, t12) DO_S( 2, 0, t02) DO_S( 2, 1, t12) DO_S( 2, 2, t22)
            #undef DO_S
        }
        #undef DO_R

        orow[r * W] = __fdividef(num, den);

        // rotate window down
        #pragma unroll
        for (int j = 0; j < 3; j++) { ra[j] = rb[j]; rb[j] = rc[j]; }
    }
}

extern "C" void kernel_launch(void* const* d_in, const int* in_sizes, int n_in,
                              void* d_out, int out_size)
{
    const float* x         = (const float*)d_in[0];
    const float* sigma_xyz = (const float*)d_in[1];
    const float* sigma_r   = (const float*)d_in[2];
    float* out = (float*)d_out;

    const int B = in_sizes[0] / (H * W);

    float* buf0;
    float* buf1;
    cudaGetSymbolAddress((void**)&buf0, g_buf0);
    cudaGetSymbolAddress((void**)&buf1, g_buf1);

    dim3 block(BX, BY, 1);
    dim3 grid(W / BX, H / BLKY, B);

    bilateral_pass<<<grid, block>>>(x,    buf0, sigma_xyz, sigma_r, 0);
    bilateral_pass<<<grid, block>>>(buf0, buf1, sigma_xyz, sigma_r, 1);
    bilateral_pass<<<grid, block>>>(buf1, out,  sigma_xyz, sigma_r, 2);
}